// round 2
// baseline (speedup 1.0000x reference)
#include <cuda_runtime.h>
#include <cstdint>

// Problem constants (fixed by the benchmark).
#define F    128      // node feature dim (l and m)
#define E    16       // edge feature dim (n)
#define KN   32       // neighbors per node
#define Q    (E * F)  // flattened contraction dim = 2048, q = n*128 + l
#define MT   16       // nodes per CTA
#define NT   256      // threads per CTA
#define SSTRIDE 20    // padded node-stride for S in smem (16B-aligned rows, <=4-way conflicts)

#define S_FLOATS   (Q * SSTRIDE)           // 40960 floats = 163840 B
#define EBUF_OFF   S_FLOATS                // edges staging: 2 nodes x 32 x 16 floats
#define EBUF_FLOATS (2 * KN * E)           // 1024
#define IBUF_OFF_B ((EBUF_OFF + EBUF_FLOATS) * 4)  // byte offset of idx buffer
#define SMEM_BYTES (IBUF_OFF_B + 2 * KN * 4)       // + 2 x 32 int32 = 168192 B

// Pre-transposed weights: W2[q*128 + m] = w[l*2048 + m*16 + n], q = n*128 + l.
__device__ float g_W2[Q * F];
// nlist dtype flag: 1 if the buffer is int64, 0 if int32. Set per launch.
__device__ int g_is64;

// ---------- packed f32x2 helpers ----------
__device__ __forceinline__ void ffma2(unsigned long long& d,
                                      unsigned long long a,
                                      unsigned long long b) {
    asm("fma.rn.f32x2 %0, %1, %2, %0;" : "+l"(d) : "l"(a), "l"(b));
}
__device__ __forceinline__ unsigned long long pk2(float x, float y) {
    unsigned long long r;
    asm("mov.b64 %0, {%1, %2};" : "=l"(r) : "f"(x), "f"(y));
    return r;
}
__device__ __forceinline__ void unpk2(float& x, float& y, unsigned long long v) {
    asm("mov.b64 {%0, %1}, %2;" : "=f"(x), "=f"(y) : "l"(v));
}

// ---------- kernel 0: detect nlist dtype ----------
// Reads only the first 32 int32 words (128 B — safe for either dtype).
// If nlist is little-endian int64 with values < 2^31, every odd word is 0.
// If int32, odd words are random indices in [0, N): P[all 16 zero] ~ 0.
__global__ void detect_idx_kernel(const int* __restrict__ nl) {
    int odd_nonzero = 0;
    if (threadIdx.x < 16) odd_nonzero = (nl[2 * threadIdx.x + 1] != 0);
    unsigned any = __ballot_sync(0xffffffffu, odd_nonzero);
    if (threadIdx.x == 0) g_is64 = (any == 0u) ? 1 : 0;
}

// ---------- kernel 1: transpose w -> g_W2 ----------
__global__ void transpose_w_kernel(const float* __restrict__ w) {
    int o = blockIdx.x * blockDim.x + threadIdx.x;   // o in [0, Q*F)
    if (o >= Q * F) return;
    int m = o & (F - 1);
    int q = o >> 7;
    int l = q & (F - 1);
    int n = q >> 7;
    g_W2[o] = w[((l << 7) + m) * E + n];
}

// ---------- kernel 2: fused gather + contraction ----------
__global__ void __launch_bounds__(NT, 1)
mp_kernel(const float* __restrict__ nodes,
          const void* __restrict__ nlist_raw,
          const float* __restrict__ edges,
          float* __restrict__ out,
          int N) {
    extern __shared__ float smem[];
    float* S  = smem;                       // [Q][SSTRIDE]
    float* eb = smem + EBUF_OFF;            // [2][KN*E]
    int*   ib = (int*)((char*)smem + IBUF_OFF_B);  // [2][KN], normalized int32

    const int tid  = threadIdx.x;
    const int l    = tid & (F - 1);         // 0..127
    const int sub  = tid >> 7;              // 0/1
    const int base = blockIdx.x * MT;
    const int is64 = g_is64;

    const long long* nl64 = (const long long*)nlist_raw;
    const int*       nl32 = (const int*)nlist_raw;

    // ================= Stage 1: S[q][v] = sum_j nodes[idx[j], l] * edges[i, j, n] =================
    for (int it = 0; it < MT / 2; ++it) {
        const int v = it * 2 + sub;         // node within tile
        const int i = base + v;
        const bool valid = (i < N);

        __syncthreads();   // protect previous iteration's eb/ib reads

        // stage edges (512 floats per node, float4 per thread) and idx (32 int32)
        if (valid) {
            ((float4*)(eb + sub * (KN * E)))[l] =
                ((const float4*)(edges + (size_t)i * (KN * E)))[l];
            if (l < KN) {
                int nb = is64 ? (int)nl64[(size_t)i * KN + l]
                              :      nl32[(size_t)i * KN + l];
                ib[sub * KN + l] = nb;
            }
        }
        __syncthreads();

        if (valid) {
            unsigned long long acc[E / 2];
            #pragma unroll
            for (int p = 0; p < E / 2; ++p) acc[p] = 0ull;

            const float* ebs = eb + sub * (KN * E);
            const int*   ibs = ib + sub * KN;

            #pragma unroll
            for (int j0 = 0; j0 < KN; j0 += 8) {
                float x[8];
                #pragma unroll
                for (int u = 0; u < 8; ++u) {
                    int nb = ibs[j0 + u];
                    x[u] = nodes[(size_t)nb * F + l];       // coalesced over l
                }
                #pragma unroll
                for (int u = 0; u < 8; ++u) {
                    unsigned long long xx = pk2(x[u], x[u]);
                    const unsigned long long* ep =
                        (const unsigned long long*)(ebs + (j0 + u) * E);
                    #pragma unroll
                    for (int p = 0; p < E / 2; ++p)
                        ffma2(acc[p], xx, ep[p]);           // n = 2p, 2p+1
                }
            }

            // write S: q = n*128 + l
            #pragma unroll
            for (int p = 0; p < E / 2; ++p) {
                float a, b;
                unpk2(a, b, acc[p]);
                S[((2 * p)     * F + l) * SSTRIDE + v] = a;
                S[((2 * p + 1) * F + l) * SSTRIDE + v] = b;
            }
        }
    }
    __syncthreads();

    // ================= Stage 2: out[i][m] = (1/K) * sum_q S[q][v] * W2[q][m] =================
    // thread: m = tid&127, node-group g = tid>>7 handles nodes g*8 .. g*8+7
    const int m = tid & (F - 1);
    const int g = tid >> 7;
    const float* Wp = g_W2 + m;
    const float* Sp = S + (g << 3);

    unsigned long long acc[4];
    #pragma unroll
    for (int p = 0; p < 4; ++p) acc[p] = 0ull;

    #pragma unroll 1
    for (int q0 = 0; q0 < Q; q0 += 16) {
        float wv[16];
        #pragma unroll
        for (int u = 0; u < 16; ++u)
            wv[u] = Wp[(q0 + u) << 7];      // 16 independent coalesced LDGs in flight
        #pragma unroll
        for (int u = 0; u < 16; ++u) {
            const unsigned long long wp = pk2(wv[u], wv[u]);
            // S row: 8 node values, broadcast LDS.128 x2 (16B aligned: q*80 + g*32 floats)
            const ulonglong2 sA = *(const ulonglong2*)(Sp + (q0 + u) * SSTRIDE);
            ffma2(acc[0], sA.x, wp);
            ffma2(acc[1], sA.y, wp);
            const ulonglong2 sB = *(const ulonglong2*)(Sp + (q0 + u) * SSTRIDE + 4);
            ffma2(acc[2], sB.x, wp);
            ffma2(acc[3], sB.y, wp);
        }
    }

    const float inv_k = 1.0f / (float)KN;
    #pragma unroll
    for (int p = 0; p < 4; ++p) {
        float a, b;
        unpk2(a, b, acc[p]);
        int i0 = base + (g << 3) + 2 * p;
        if (i0 < N)     out[(size_t)i0 * F + m]       = a * inv_k;
        if (i0 + 1 < N) out[(size_t)(i0 + 1) * F + m] = b * inv_k;
    }
}

// ---------- launch ----------
extern "C" void kernel_launch(void* const* d_in, const int* in_sizes, int n_in,
                              void* d_out, int out_size) {
    // Identify inputs by element count (robust to metadata ordering):
    //   w     = F*F*E = 262144
    //   edges = largest = N*K*E
    //   nodes = edges / 4  (N*F)
    //   nlist = edges / 16 (N*K)
    int iw = -1, ie = -1, ino = -1, inl = -1;
    long long emax = -1;
    for (int t = 0; t < n_in; ++t)
        if (in_sizes[t] == F * F * E) iw = t;
    for (int t = 0; t < n_in; ++t)
        if (t != iw && (long long)in_sizes[t] > emax) { emax = in_sizes[t]; ie = t; }
    for (int t = 0; t < n_in; ++t) {
        if (t == iw || t == ie) continue;
        if ((long long)in_sizes[t] * 4 == emax)  ino = t;
        if ((long long)in_sizes[t] * 16 == emax) inl = t;
    }
    // Fallback to declared order if identification failed.
    if (iw < 0 || ie < 0 || ino < 0 || inl < 0) { ino = 0; inl = 1; ie = 2; iw = 3; }

    const float* nodes = (const float*)d_in[ino];
    const void*  nlist = d_in[inl];
    const float* edges = (const float*)d_in[ie];
    const float* w     = (const float*)d_in[iw];
    float*       out   = (float*)d_out;

    const int N = in_sizes[ino] / F;

    detect_idx_kernel<<<1, 32>>>((const int*)nlist);
    transpose_w_kernel<<<(Q * F + NT - 1) / NT, NT>>>(w);

    cudaFuncSetAttribute(mp_kernel,
                         cudaFuncAttributeMaxDynamicSharedMemorySize,
                         SMEM_BYTES);
    const int blocks = (N + MT - 1) / MT;
    mp_kernel<<<blocks, NT, SMEM_BYTES>>>(nodes, nlist, edges, out, N);
}

// round 3
// speedup vs baseline: 1.1102x; 1.1102x over previous
#include <cuda_runtime.h>
#include <cstdint>

#define F    128
#define E    16
#define KN   32
#define Q    (E * F)   // 2048
#define MT   16        // nodes per CTA
#define NT   256
#define QH   (Q / 2)   // 1024 per q-half
#define SSTRIDE 20     // padded node-stride for S rows (16B-aligned, <=4-way conflicts)

#define S_FLOATS    (Q * SSTRIDE)                  // 40960 floats
#define EBUF_OFF    S_FLOATS
#define EBUF_FLOATS (2 * KN * E)                   // 1024
#define IBUF_OFF_B  ((EBUF_OFF + EBUF_FLOATS) * 4)
#define SMEM_BYTES  (IBUF_OFF_B + 2 * KN * 4)      // 168192 B

// Pre-transposed weights: W2[q*128 + m] = w[l*2048 + m*16 + n], q = n*128 + l.
__device__ float g_W2[Q * F];
__device__ int g_is64;   // nlist dtype flag

// ---------- packed f32x2 helpers ----------
__device__ __forceinline__ void ffma2(unsigned long long& d,
                                      unsigned long long a,
                                      unsigned long long b) {
    asm("fma.rn.f32x2 %0, %1, %2, %0;" : "+l"(d) : "l"(a), "l"(b));
}
__device__ __forceinline__ unsigned long long pk2(float x, float y) {
    unsigned long long r;
    asm("mov.b64 %0, {%1, %2};" : "=l"(r) : "f"(x), "f"(y));
    return r;
}
__device__ __forceinline__ void unpk2(float& x, float& y, unsigned long long v) {
    asm("mov.b64 {%0, %1}, %2;" : "=f"(x), "=f"(y) : "l"(v));
}

// ---------- kernel 1: setup = transpose w -> g_W2, plus nlist dtype detect ----------
__global__ void setup_kernel(const float* __restrict__ w,
                             const int* __restrict__ nl) {
    if (blockIdx.x == 0 && threadIdx.x < 32) {
        // If nlist is little-endian int64 (values < 2^31), every odd 32-bit word
        // of the first 32 words is zero. For int32 data P[all zero] ~ (1/N)^16.
        int odd_nonzero = (threadIdx.x < 16) ? (nl[2 * threadIdx.x + 1] != 0) : 0;
        unsigned any = __ballot_sync(0xffffffffu, odd_nonzero);
        if (threadIdx.x == 0) g_is64 = (any == 0u) ? 1 : 0;
    }
    int o = blockIdx.x * blockDim.x + threadIdx.x;
    if (o >= Q * F) return;
    int m = o & (F - 1);
    int q = o >> 7;
    int l = q & (F - 1);
    int n = q >> 7;
    g_W2[o] = w[((l << 7) + m) * E + n];
}

// ---------- kernel 2: fused gather + contraction ----------
__global__ void __launch_bounds__(NT, 1)
mp_kernel(const float* __restrict__ nodes,
          const void* __restrict__ nlist_raw,
          const float* __restrict__ edges,
          float* __restrict__ out,
          int N) {
    extern __shared__ float smem[];
    float* S  = smem;                                // [Q][SSTRIDE]
    float* eb = smem + EBUF_OFF;                     // [2][KN*E]
    int*   ib = (int*)((char*)smem + IBUF_OFF_B);    // [2][KN]

    const int tid  = threadIdx.x;
    const int l    = tid & (F - 1);
    const int sub  = tid >> 7;       // 0/1
    const int base = blockIdx.x * MT;
    const int is64 = g_is64;

    const long long* nl64 = (const long long*)nlist_raw;
    const int*       nl32 = (const int*)nlist_raw;

    // ===== Stage 1: S[q][v] = sum_j nodes[idx[v][j], l] * edges[base+v, j, n] =====
    for (int it = 0; it < MT / 2; ++it) {
        const int v = it * 2 + sub;
        const int i = base + v;
        const bool valid = (i < N);

        __syncthreads();   // protect previous iteration's eb/ib

        if (valid) {
            ((float4*)(eb + sub * (KN * E)))[l] =
                ((const float4*)(edges + (size_t)i * (KN * E)))[l];
            if (l < KN) {
                int nb = is64 ? (int)nl64[(size_t)i * KN + l]
                              :      nl32[(size_t)i * KN + l];
                ib[sub * KN + l] = nb;
            }
        }
        __syncthreads();

        if (valid) {
            unsigned long long acc[E / 2];
            #pragma unroll
            for (int p = 0; p < E / 2; ++p) acc[p] = 0ull;

            const float* ebs = eb + sub * (KN * E);
            const int*   ibs = ib + sub * KN;

            #pragma unroll
            for (int j0 = 0; j0 < KN; j0 += 8) {
                float x[8];
                #pragma unroll
                for (int u = 0; u < 8; ++u) {
                    int nb = ibs[j0 + u];
                    x[u] = nodes[(size_t)nb * F + l];   // coalesced over l
                }
                #pragma unroll
                for (int u = 0; u < 8; ++u) {
                    unsigned long long xx = pk2(x[u], x[u]);
                    const unsigned long long* ep =
                        (const unsigned long long*)(ebs + (j0 + u) * E);
                    #pragma unroll
                    for (int p = 0; p < E / 2; ++p)
                        ffma2(acc[p], xx, ep[p]);
                }
            }

            #pragma unroll
            for (int p = 0; p < E / 2; ++p) {
                float a, b;
                unpk2(a, b, acc[p]);
                S[((2 * p)     * F + l) * SSTRIDE + v] = a;
                S[((2 * p + 1) * F + l) * SSTRIDE + v] = b;
            }
        }
    }
    __syncthreads();

    // ===== Stage 2: out[base+v][m] = (1/K) * sum_q S[q][v] * W2[q][m] =====
    // q-split: thread = (m, q-half). Each W2 value is loaded exactly ONCE per CTA.
    const int m  = tid & (F - 1);
    const int qh = tid >> 7;                   // 0/1
    const int qbase = qh << 10;                // 0 or 1024
    const float* Wp = g_W2 + (qbase << 7) + m;
    const float* Sh = S + qbase * SSTRIDE;

    unsigned long long acc[8];                 // 16 node accumulators
    #pragma unroll
    for (int p = 0; p < 8; ++p) acc[p] = 0ull;

    #pragma unroll 1
    for (int q0 = 0; q0 < QH; q0 += 16) {
        float wv[16];
        #pragma unroll
        for (int u = 0; u < 16; ++u)
            wv[u] = Wp[(q0 + u) << 7];         // 16 coalesced LDGs in flight
        #pragma unroll
        for (int u = 0; u < 16; ++u) {
            const unsigned long long wp = pk2(wv[u], wv[u]);
            const float* row = Sh + (q0 + u) * SSTRIDE;
            const ulonglong2 sA = *(const ulonglong2*)(row);       // nodes 0..3
            const ulonglong2 sB = *(const ulonglong2*)(row + 4);   // nodes 4..7
            const ulonglong2 sC = *(const ulonglong2*)(row + 8);   // nodes 8..11
            const ulonglong2 sD = *(const ulonglong2*)(row + 12);  // nodes 12..15
            ffma2(acc[0], sA.x, wp);  ffma2(acc[1], sA.y, wp);
            ffma2(acc[2], sB.x, wp);  ffma2(acc[3], sB.y, wp);
            ffma2(acc[4], sC.x, wp);  ffma2(acc[5], sC.y, wp);
            ffma2(acc[6], sD.x, wp);  ffma2(acc[7], sD.y, wp);
        }
    }

    // Cross-half reduction through smem (S region is free now).
    __syncthreads();
    unsigned long long* red = (unsigned long long*)S;   // [128][8]
    if (qh == 1) {
        #pragma unroll
        for (int p = 0; p < 8; ++p) red[m * 8 + p] = acc[p];
    }
    __syncthreads();
    if (qh == 0) {
        const float inv_k = 1.0f / (float)KN;
        #pragma unroll
        for (int p = 0; p < 8; ++p) {
            float a0, b0, a1, b1;
            unpk2(a0, b0, acc[p]);
            unpk2(a1, b1, red[m * 8 + p]);
            int i0 = base + 2 * p;
            if (i0 < N)     out[(size_t)i0 * F + m]       = (a0 + a1) * inv_k;
            if (i0 + 1 < N) out[(size_t)(i0 + 1) * F + m] = (b0 + b1) * inv_k;
        }
    }
}

// ---------- launch ----------
extern "C" void kernel_launch(void* const* d_in, const int* in_sizes, int n_in,
                              void* d_out, int out_size) {
    // Identify inputs by element count:
    //   w = F*F*E = 262144, edges = largest, nodes = edges/4, nlist = edges/16.
    int iw = -1, ie = -1, ino = -1, inl = -1;
    long long emax = -1;
    for (int t = 0; t < n_in; ++t)
        if (in_sizes[t] == F * F * E) iw = t;
    for (int t = 0; t < n_in; ++t)
        if (t != iw && (long long)in_sizes[t] > emax) { emax = in_sizes[t]; ie = t; }
    for (int t = 0; t < n_in; ++t) {
        if (t == iw || t == ie) continue;
        if ((long long)in_sizes[t] * 4 == emax)  ino = t;
        if ((long long)in_sizes[t] * 16 == emax) inl = t;
    }
    if (iw < 0 || ie < 0 || ino < 0 || inl < 0) { ino = 0; inl = 1; ie = 2; iw = 3; }

    const float* nodes = (const float*)d_in[ino];
    const void*  nlist = d_in[inl];
    const float* edges = (const float*)d_in[ie];
    const float* w     = (const float*)d_in[iw];
    float*       out   = (float*)d_out;

    const int N = in_sizes[ino] / F;

    setup_kernel<<<(Q * F + NT - 1) / NT, NT>>>(w, (const int*)nlist);

    cudaFuncSetAttribute(mp_kernel,
                         cudaFuncAttributeMaxDynamicSharedMemorySize,
                         SMEM_BYTES);
    const int blocks = (N + MT - 1) / MT;
    mp_kernel<<<blocks, NT, SMEM_BYTES>>>(nodes, nlist, edges, out, N);
}

// round 4
// speedup vs baseline: 1.5685x; 1.4128x over previous
#include <cuda_runtime.h>
#include <cstdint>

#define F    128
#define E    16
#define KN   32
#define Q    (E * F)   // 2048
#define MT   16        // nodes per CTA
#define NT   256
#define SSTRIDE 20     // padded node-stride for S rows (16B-aligned, <=4-way STS conflicts)

#define S_FLOATS    (Q * SSTRIDE)                  // 40960 floats
#define EBUF_OFF    S_FLOATS
#define EBUF_FLOATS (2 * KN * E)                   // 1024
#define IBUF_OFF_B  ((EBUF_OFF + EBUF_FLOATS) * 4)
#define SMEM_BYTES  (IBUF_OFF_B + 2 * KN * 4)      // 168192 B

// Pre-transposed weights: W2[q*128 + m] = w[l*2048 + m*16 + n], q = n*128 + l.
__device__ float g_W2[Q * F];
__device__ int g_is64;   // nlist dtype flag

// ---------- packed f32x2 helpers ----------
__device__ __forceinline__ void ffma2(unsigned long long& d,
                                      unsigned long long a,
                                      unsigned long long b) {
    asm("fma.rn.f32x2 %0, %1, %2, %0;" : "+l"(d) : "l"(a), "l"(b));
}
__device__ __forceinline__ unsigned long long pk2(float x, float y) {
    unsigned long long r;
    asm("mov.b64 %0, {%1, %2};" : "=l"(r) : "f"(x), "f"(y));
    return r;
}
__device__ __forceinline__ void unpk2(float& x, float& y, unsigned long long v) {
    asm("mov.b64 {%0, %1}, %2;" : "=f"(x), "=f"(y) : "l"(v));
}

// ---------- kernel 1: setup = transpose w -> g_W2, plus nlist dtype detect ----------
__global__ void setup_kernel(const float* __restrict__ w,
                             const int* __restrict__ nl) {
    if (blockIdx.x == 0 && threadIdx.x < 32) {
        int odd_nonzero = (threadIdx.x < 16) ? (nl[2 * threadIdx.x + 1] != 0) : 0;
        unsigned any = __ballot_sync(0xffffffffu, odd_nonzero);
        if (threadIdx.x == 0) g_is64 = (any == 0u) ? 1 : 0;
    }
    int o = blockIdx.x * blockDim.x + threadIdx.x;
    if (o >= Q * F) return;
    int m = o & (F - 1);
    int q = o >> 7;
    int l = q & (F - 1);
    int n = q >> 7;
    g_W2[o] = w[((l << 7) + m) * E + n];
}

// ---------- kernel 2: fused gather + contraction ----------
__global__ void __launch_bounds__(NT, 1)
mp_kernel(const float* __restrict__ nodes,
          const void* __restrict__ nlist_raw,
          const float* __restrict__ edges,
          float* __restrict__ out,
          int N) {
    extern __shared__ float smem[];
    float* S  = smem;                                // [Q][SSTRIDE]
    float* eb = smem + EBUF_OFF;                     // [2][KN*E]
    int*   ib = (int*)((char*)smem + IBUF_OFF_B);    // [2][KN]

    const int tid  = threadIdx.x;
    const int base = blockIdx.x * MT;
    const int is64 = g_is64;

    const long long* nl64 = (const long long*)nlist_raw;
    const int*       nl32 = (const int*)nlist_raw;

    // ===== Stage 1: S[q][v] = sum_j nodes[idx[v][j], l] * edges[base+v, j, n] =====
    {
        const int l   = tid & (F - 1);
        const int sub = tid >> 7;       // 0/1
        for (int it = 0; it < MT / 2; ++it) {
            const int v = it * 2 + sub;
            const int i = base + v;
            const bool valid = (i < N);

            __syncthreads();   // protect previous iteration's eb/ib

            if (valid) {
                ((float4*)(eb + sub * (KN * E)))[l] =
                    ((const float4*)(edges + (size_t)i * (KN * E)))[l];
                if (l < KN) {
                    int nb = is64 ? (int)nl64[(size_t)i * KN + l]
                                  :      nl32[(size_t)i * KN + l];
                    ib[sub * KN + l] = nb;
                }
            }
            __syncthreads();

            if (valid) {
                unsigned long long acc[E / 2];
                #pragma unroll
                for (int p = 0; p < E / 2; ++p) acc[p] = 0ull;

                const float* ebs = eb + sub * (KN * E);
                const int*   ibs = ib + sub * KN;

                #pragma unroll
                for (int j0 = 0; j0 < KN; j0 += 8) {
                    float x[8];
                    #pragma unroll
                    for (int u = 0; u < 8; ++u) {
                        int nb = ibs[j0 + u];
                        x[u] = nodes[(size_t)nb * F + l];   // coalesced over l
                    }
                    #pragma unroll
                    for (int u = 0; u < 8; ++u) {
                        unsigned long long xx = pk2(x[u], x[u]);
                        const unsigned long long* ep =
                            (const unsigned long long*)(ebs + (j0 + u) * E);
                        #pragma unroll
                        for (int p = 0; p < E / 2; ++p)
                            ffma2(acc[p], xx, ep[p]);
                    }
                }

                #pragma unroll
                for (int p = 0; p < E / 2; ++p) {
                    float a, b;
                    unpk2(a, b, acc[p]);
                    S[((2 * p)     * F + l) * SSTRIDE + v] = a;
                    S[((2 * p + 1) * F + l) * SSTRIDE + v] = b;
                }
            }
        }
        __syncthreads();
    }

    // ===== Stage 2: register-tiled GEMM: out[v][m] = (1/K) sum_q S[q][v] * W2[q][m] =====
    // thread = (mg = tid&31 -> m = 4*mg..4*mg+3, qs = tid>>5 -> q in [qs*256, qs*256+256)).
    // Per q: 1 LDG.128 (W, 4 m) + 4 LDS.128 (16 nodes) -> 32 FFMA2.
    const int mg = tid & 31;
    const int qs = tid >> 5;
    const float4* W4 = ((const float4*)g_W2) + mg;   // + q*32
    const float*  Sh = S + (qs << 8) * SSTRIDE;

    unsigned long long acc[4][8];   // [m'][node-pair]
    #pragma unroll
    for (int mp = 0; mp < 4; ++mp)
        #pragma unroll
        for (int p = 0; p < 8; ++p) acc[mp][p] = 0ull;

    #pragma unroll 1
    for (int q0 = 0; q0 < 256; q0 += 8) {
        float4 wv[8];
        #pragma unroll
        for (int u = 0; u < 8; ++u)
            wv[u] = W4[(size_t)(((qs << 8) + q0 + u) << 5)];   // coalesced LDG.128 x8 in flight
        #pragma unroll
        for (int u = 0; u < 8; ++u) {
            const float* row = Sh + (q0 + u) * SSTRIDE;
            const ulonglong2 sA = *(const ulonglong2*)(row);        // nodes 0..3
            const ulonglong2 sB = *(const ulonglong2*)(row + 4);    // nodes 4..7
            const ulonglong2 sC = *(const ulonglong2*)(row + 8);    // nodes 8..11
            const ulonglong2 sD = *(const ulonglong2*)(row + 12);   // nodes 12..15
            const unsigned long long s[8] = {sA.x, sA.y, sB.x, sB.y,
                                             sC.x, sC.y, sD.x, sD.y};
            unsigned long long wp[4];
            wp[0] = pk2(wv[u].x, wv[u].x);
            wp[1] = pk2(wv[u].y, wv[u].y);
            wp[2] = pk2(wv[u].z, wv[u].z);
            wp[3] = pk2(wv[u].w, wv[u].w);
            #pragma unroll
            for (int mp = 0; mp < 4; ++mp)
                #pragma unroll
                for (int p = 0; p < 8; ++p)
                    ffma2(acc[mp][p], s[p], wp[mp]);
        }
    }

    // ===== Cross-qs reduction through smem (S region is dead now) =====
    __syncthreads();
    unsigned long long* red = (unsigned long long*)smem;  // [(m'*8+p)*265 + qs*33 + mg]
    #pragma unroll
    for (int mp = 0; mp < 4; ++mp)
        #pragma unroll
        for (int p = 0; p < 8; ++p)
            red[(mp * 8 + p) * 265 + qs * 33 + mg] = acc[mp][p];
    __syncthreads();

    const float inv_k = 1.0f / (float)KN;
    #pragma unroll
    for (int oi = 0; oi < 4; ++oi) {
        const int id  = oi * 256 + tid;      // 0..1023 = (m, node-pair p)
        const int m   = id >> 3;
        const int p   = id & 7;
        const int mgr = m >> 2;
        const int mpr = m & 3;
        float a = 0.f, b = 0.f;
        #pragma unroll
        for (int q2 = 0; q2 < 8; ++q2) {
            float x, y;
            unpk2(x, y, red[(mpr * 8 + p) * 265 + q2 * 33 + mgr]);
            a += x; b += y;
        }
        const int i0 = base + 2 * p;
        if (i0 < N)     out[(size_t)i0 * F + m]       = a * inv_k;
        if (i0 + 1 < N) out[(size_t)(i0 + 1) * F + m] = b * inv_k;
    }
}

// ---------- launch ----------
extern "C" void kernel_launch(void* const* d_in, const int* in_sizes, int n_in,
                              void* d_out, int out_size) {
    // Identify inputs by element count:
    //   w = F*F*E = 262144, edges = largest, nodes = edges/4, nlist = edges/16.
    int iw = -1, ie = -1, ino = -1, inl = -1;
    long long emax = -1;
    for (int t = 0; t < n_in; ++t)
        if (in_sizes[t] == F * F * E) iw = t;
    for (int t = 0; t < n_in; ++t)
        if (t != iw && (long long)in_sizes[t] > emax) { emax = in_sizes[t]; ie = t; }
    for (int t = 0; t < n_in; ++t) {
        if (t == iw || t == ie) continue;
        if ((long long)in_sizes[t] * 4 == emax)  ino = t;
        if ((long long)in_sizes[t] * 16 == emax) inl = t;
    }
    if (iw < 0 || ie < 0 || ino < 0 || inl < 0) { ino = 0; inl = 1; ie = 2; iw = 3; }

    const float* nodes = (const float*)d_in[ino];
    const void*  nlist = d_in[inl];
    const float* edges = (const float*)d_in[ie];
    const float* w     = (const float*)d_in[iw];
    float*       out   = (float*)d_out;

    const int N = in_sizes[ino] / F;

    setup_kernel<<<(Q * F + NT - 1) / NT, NT>>>(w, (const int*)nlist);

    cudaFuncSetAttribute(mp_kernel,
                         cudaFuncAttributeMaxDynamicSharedMemorySize,
                         SMEM_BYTES);
    const int blocks = (N + MT - 1) / MT;
    mp_kernel<<<blocks, NT, SMEM_BYTES>>>(nodes, nlist, edges, out, N);
}